// round 14
// baseline (speedup 1.0000x reference)
#include <cuda_runtime.h>
#include <stdint.h>

#define BB 64
#define NN 512
#define DD 256
#define EE 128
#define NITER 20

// ---------------- device scratch (no allocations allowed) ----------------
__device__ float g_a [BB * NN * EE];            // 16 MB  a = (x_out @ W_a) * w_aff
__device__ float g_bm[BB * NN * EE];            // 16 MB  b = x_in @ W_b
__device__ float g_K [BB * NN * NN];            // 67 MB  E, then scaled K in place
__device__ float g_rp[4][BB * NN];              // per-jblock rowsum partials of E
__device__ float g_cp[4][BB * NN];              // per-iblock colsum partials of E
__device__ float g_u [BB * NN];                 // row scalings
__device__ float g_part[2][8][BB * NN];         // ping-pong per-slab colsum partials
__device__ int   g_mask_mode;                   // 0=int32, 1=float32, 2=byte

// ---------------- f32x2 helpers (Blackwell packed fp32 FMA) ----------------
__device__ __forceinline__ unsigned long long pk2(float lo, float hi) {
    unsigned long long r;
    asm("mov.b64 %0, {%1,%2};" : "=l"(r) : "f"(lo), "f"(hi));
    return r;
}
__device__ __forceinline__ float2 upk2(unsigned long long v) {
    float2 f;
    asm("mov.b64 {%0,%1}, %2;" : "=f"(f.x), "=f"(f.y) : "l"(v));
    return f;
}
__device__ __forceinline__ unsigned long long fma2(unsigned long long a,
                                                   unsigned long long b,
                                                   unsigned long long c) {
    unsigned long long d;
    asm("fma.rn.f32x2 %0, %1, %2, %3;" : "=l"(d) : "l"(a), "l"(b), "l"(c));
    return d;
}

// ---------------- init: detect mask dtype ----------------------------------
// bool mask may arrive as int32, float32, or raw bytes; classify by pattern.
__global__ void k_init(const void* __restrict__ mask) {
    int t = threadIdx.x;                          // 1 block, 512 threads
    __shared__ int okInt, okFlt;
    if (t == 0) { okInt = 1; okFlt = 1; }
    __syncthreads();
    const int*   mi = (const int*)mask;
    const float* mf = (const float*)mask;
    int li = 1, lf = 1;
    for (int q = t; q < 2048; q += 512) {         // 8 KB probe, safe for all layouts
        int v = mi[q];   if (v != 0 && v != 1)     li = 0;
        float f = mf[q]; if (f != 0.f && f != 1.f) lf = 0;
    }
    if (!li) atomicAnd(&okInt, 0);
    if (!lf) atomicAnd(&okFlt, 0);
    __syncthreads();
    if (t == 0) g_mask_mode = okInt ? 0 : (okFlt ? 1 : 2);
}

// ---------------- K1: a = (x_out @ W_a)*w_aff  and  b = x_in @ W_b ---------
__global__ __launch_bounds__(256) void k_gemm_ab(
    const float* __restrict__ nodeIn, const void* __restrict__ mask,
    const float* __restrict__ nodeOut, const float* __restrict__ pad,
    const float* __restrict__ pos, const float* __restrict__ Wa,
    const float* __restrict__ Wb, const float* __restrict__ waff)
{
    __shared__ __align__(16) float Xs[32][66];    // k-major, transposed X tile
    __shared__ __align__(16) float Ws[32][128];   // [k][col]
    int tid  = threadIdx.x;
    int z    = blockIdx.z;                        // 0 -> a, 1 -> b
    int row0 = blockIdx.x * 64;
    int colg = tid & 31;                          // 32 col groups of 4
    int rowg = tid >> 5;                          // 8 row groups of 8
    const float* W = z ? Wb : Wa;
    int mode = g_mask_mode;

    unsigned long long acc[4][4];
    #pragma unroll
    for (int p = 0; p < 4; p++)
        #pragma unroll
        for (int c = 0; c < 4; c++) acc[p][c] = 0ull;

    for (int kb = 0; kb < 8; kb++) {
        int k0 = kb * 32;
        #pragma unroll
        for (int it = 0; it < 8; it++) {          // 2048 floats of X (with transform)
            int l = tid + it * 256;
            int kk = l & 31, r = l >> 5;
            int grow = row0 + r;
            float v;
            if (z == 0) {
                v = nodeOut[grow * DD + k0 + kk] + pos[(grow & (NN - 1)) * DD + k0 + kk];
            } else {
                bool m;
                if (mode == 0)      m = ((const int*)mask)[grow] != 0;
                else if (mode == 1) m = ((const float*)mask)[grow] != 0.f;
                else                m = ((const unsigned char*)mask)[grow] != 0;
                v = m ? pad[k0 + kk] : nodeIn[grow * DD + k0 + kk];
            }
            Xs[kk][r] = v;
        }
        #pragma unroll
        for (int it = 0; it < 4; it++) {          // 4096 floats of W as float4
            int l  = tid + it * 256;
            int kk = l >> 5;
            int c4 = (l & 31) * 4;
            *(float4*)&Ws[kk][c4] = *(const float4*)&W[(k0 + kk) * EE + c4];
        }
        __syncthreads();
        #pragma unroll
        for (int kk = 0; kk < 32; kk++) {
            unsigned long long a2[4];
            #pragma unroll
            for (int p = 0; p < 4; p++)
                a2[p] = *(const unsigned long long*)&Xs[kk][rowg * 8 + 2 * p];
            float4 b4 = *(const float4*)&Ws[kk][colg * 4];
            unsigned long long bb0 = pk2(b4.x, b4.x), bb1 = pk2(b4.y, b4.y);
            unsigned long long bb2 = pk2(b4.z, b4.z), bb3 = pk2(b4.w, b4.w);
            #pragma unroll
            for (int p = 0; p < 4; p++) {
                acc[p][0] = fma2(a2[p], bb0, acc[p][0]);
                acc[p][1] = fma2(a2[p], bb1, acc[p][1]);
                acc[p][2] = fma2(a2[p], bb2, acc[p][2]);
                acc[p][3] = fma2(a2[p], bb3, acc[p][3]);
            }
        }
        __syncthreads();
    }
    float w0 = 1.f, w1 = 1.f, w2 = 1.f, w3 = 1.f;
    if (z == 0) {
        w0 = waff[colg * 4 + 0]; w1 = waff[colg * 4 + 1];
        w2 = waff[colg * 4 + 2]; w3 = waff[colg * 4 + 3];
    }
    float* out = z ? g_bm : g_a;
    #pragma unroll
    for (int p = 0; p < 4; p++) {
        float2 c0 = upk2(acc[p][0]), c1 = upk2(acc[p][1]);
        float2 c2 = upk2(acc[p][2]), c3 = upk2(acc[p][3]);
        int r0 = row0 + rowg * 8 + 2 * p;
        float4 lo = make_float4(c0.x * w0, c1.x * w1, c2.x * w2, c3.x * w3);
        float4 hi = make_float4(c0.y * w0, c1.y * w1, c2.y * w2, c3.y * w3);
        *(float4*)&out[(size_t)r0 * EE + colg * 4]       = lo;
        *(float4*)&out[(size_t)(r0 + 1) * EE + colg * 4] = hi;
    }
}

// ---------------- K2: E = exp(a·b^T + b_aff), deterministic partial sums ---
// grid (jb=4, ib=4, b=64); block computes a 128x128 tile of E, writes it to
// g_K, and emits rowsum partials (per jb) and colsum partials (per ib) with
// fixed-order reductions (no atomics anywhere).
__global__ __launch_bounds__(256, 2) void k_aff_exp(const float* __restrict__ baff_p)
{
    __shared__ __align__(16) float As[32][132];   // [e][i]
    __shared__ __align__(16) float Bs[32][132];   // [e][j]
    int tid = threadIdx.x;
    int b  = blockIdx.z;
    int i0 = blockIdx.y * 128, j0 = blockIdx.x * 128;
    int tx = tid & 15, ty = tid >> 4;             // cols: tx*4 and 64+tx*4 ; rows: ty*8

    unsigned long long acc[4][8];
    #pragma unroll
    for (int p = 0; p < 4; p++)
        #pragma unroll
        for (int c = 0; c < 8; c++) acc[p][c] = 0ull;

    const float* Ab = g_a  + (size_t)(b * NN + i0) * EE;
    const float* Bb = g_bm + (size_t)(b * NN + j0) * EE;

    for (int kb = 0; kb < 4; kb++) {
        int e0 = kb * 32;
        #pragma unroll
        for (int it = 0; it < 16; it++) {         // 4096 floats each, transposed
            int l = tid + it * 256;
            int e = l & 31, r = l >> 5;
            As[e][r] = Ab[r * EE + e0 + e];
            Bs[e][r] = Bb[r * EE + e0 + e];
        }
        __syncthreads();
        #pragma unroll
        for (int e = 0; e < 32; e++) {
            unsigned long long a2[4];
            #pragma unroll
            for (int p = 0; p < 4; p++)
                a2[p] = *(const unsigned long long*)&As[e][ty * 8 + 2 * p];
            float4 bA = *(const float4*)&Bs[e][tx * 4];
            float4 bB = *(const float4*)&Bs[e][64 + tx * 4];
            unsigned long long bb[8];
            bb[0] = pk2(bA.x, bA.x); bb[1] = pk2(bA.y, bA.y);
            bb[2] = pk2(bA.z, bA.z); bb[3] = pk2(bA.w, bA.w);
            bb[4] = pk2(bB.x, bB.x); bb[5] = pk2(bB.y, bB.y);
            bb[6] = pk2(bB.z, bB.z); bb[7] = pk2(bB.w, bB.w);
            #pragma unroll
            for (int p = 0; p < 4; p++)
                #pragma unroll
                for (int c = 0; c < 8; c++)
                    acc[p][c] = fma2(a2[p], bb[c], acc[p][c]);
        }
        __syncthreads();
    }

    float baff = *baff_p;
    float rs[8];
    #pragma unroll
    for (int r = 0; r < 8; r++) rs[r] = 0.f;
    float csA[4] = {0.f, 0.f, 0.f, 0.f}, csB[4] = {0.f, 0.f, 0.f, 0.f};
    float* Kb = g_K + (size_t)b * NN * NN;

    #pragma unroll
    for (int p = 0; p < 4; p++) {
        float2 vA[4], vB[4];
        #pragma unroll
        for (int c = 0; c < 4; c++) { vA[c] = upk2(acc[p][c]); vB[c] = upk2(acc[p][4 + c]); }
        float4 loA, hiA, loB, hiB;
        loA.x = __expf(vA[0].x + baff); loA.y = __expf(vA[1].x + baff);
        loA.z = __expf(vA[2].x + baff); loA.w = __expf(vA[3].x + baff);
        hiA.x = __expf(vA[0].y + baff); hiA.y = __expf(vA[1].y + baff);
        hiA.z = __expf(vA[2].y + baff); hiA.w = __expf(vA[3].y + baff);
        loB.x = __expf(vB[0].x + baff); loB.y = __expf(vB[1].x + baff);
        loB.z = __expf(vB[2].x + baff); loB.w = __expf(vB[3].x + baff);
        hiB.x = __expf(vB[0].y + baff); hiB.y = __expf(vB[1].y + baff);
        hiB.z = __expf(vB[2].y + baff); hiB.w = __expf(vB[3].y + baff);
        int il = ty * 8 + 2 * p;
        rs[2 * p]     += loA.x + loA.y + loA.z + loA.w + loB.x + loB.y + loB.z + loB.w;
        rs[2 * p + 1] += hiA.x + hiA.y + hiA.z + hiA.w + hiB.x + hiB.y + hiB.z + hiB.w;
        csA[0] += loA.x + hiA.x; csA[1] += loA.y + hiA.y;
        csA[2] += loA.z + hiA.z; csA[3] += loA.w + hiA.w;
        csB[0] += loB.x + hiB.x; csB[1] += loB.y + hiB.y;
        csB[2] += loB.z + hiB.z; csB[3] += loB.w + hiB.w;
        *(float4*)&Kb[(size_t)(i0 + il) * NN + j0 + tx * 4]           = loA;
        *(float4*)&Kb[(size_t)(i0 + il) * NN + j0 + 64 + tx * 4]      = loB;
        *(float4*)&Kb[(size_t)(i0 + il + 1) * NN + j0 + tx * 4]       = hiA;
        *(float4*)&Kb[(size_t)(i0 + il + 1) * NN + j0 + 64 + tx * 4]  = hiB;
    }

    // ---- deterministic row partials: butterfly over the 16-lane tx group ----
    #pragma unroll
    for (int r8 = 0; r8 < 8; r8++) {
        float v = rs[r8];
        v += __shfl_xor_sync(0xffffffffu, v, 1);
        v += __shfl_xor_sync(0xffffffffu, v, 2);
        v += __shfl_xor_sync(0xffffffffu, v, 4);
        v += __shfl_xor_sync(0xffffffffu, v, 8);
        rs[r8] = v;                                // whole 16-group holds the sum
    }
    if (tx == 0) {
        float* rp = &g_rp[blockIdx.x][0] + b * NN + i0;
        #pragma unroll
        for (int p = 0; p < 4; p++) {
            rp[ty * 8 + 2 * p]     = rs[2 * p];
            rp[ty * 8 + 2 * p + 1] = rs[2 * p + 1];
        }
    }

    // ---- deterministic col partials: per-ty smem rows, fixed-order sum ------
    __syncthreads();                               // As reads done; reuse its smem
    float* colp = &As[0][0];                       // [16][132] layout
    #pragma unroll
    for (int c = 0; c < 4; c++) {
        colp[ty * 132 + tx * 4 + c]      = csA[c];
        colp[ty * 132 + 64 + tx * 4 + c] = csB[c];
    }
    __syncthreads();
    if (tid < 128) {
        float s = 0.f;
        #pragma unroll
        for (int yy = 0; yy < 16; yy++) s += colp[yy * 132 + tid];
        g_cp[blockIdx.y][b * NN + j0 + tid] = s;
    }
}

// ---------------- Sinkhorn iteration kernels -------------------------------
// Each block: one 64-row slab of one batch. 256 threads = 8 warps x 32 lanes.
// One pass over K computes BOTH u=1/(Kv) and the slab's contribution to the
// column sums s = K^T u (no atomics; per-slab partials in g_part).

// Iteration 0 also applies the (c_i + d_j) scaling to K in place (v = 1).
__global__ __launch_bounds__(256) void k_iter0() {
    __shared__ __align__(16) float dloc[NN];
    __shared__ __align__(16) float colsm[8][NN];    // per-warp column partials
    int b = blockIdx.y, ic = blockIdx.x, tid = threadIdx.x;
    int w = tid >> 5, lane = tid & 31;
    #pragma unroll
    for (int h = 0; h < 2; h++) {
        int j = tid + h * 256;
        float s = g_cp[0][b * NN + j] + g_cp[1][b * NN + j]
                + g_cp[2][b * NN + j] + g_cp[3][b * NN + j];
        dloc[j] = 0.5f / s;
    }
    __syncthreads();
    const float4* dl4 = (const float4*)dloc;
    float4 d4c[4];
    #pragma unroll
    for (int q = 0; q < 4; q++) d4c[q] = dl4[lane + 32 * q];

    float4 colacc[4];
    #pragma unroll
    for (int q = 0; q < 4; q++) colacc[q] = make_float4(0.f, 0.f, 0.f, 0.f);

    #pragma unroll 4
    for (int rr = 0; rr < 8; rr++) {
        int i = ic * 64 + w * 8 + rr;
        float rsum = g_rp[0][b * NN + i] + g_rp[1][b * NN + i]
                   + g_rp[2][b * NN + i] + g_rp[3][b * NN + i];
        float ci = 0.5f / rsum;
        float4* row = (float4*)(g_K + ((size_t)b * NN + i) * NN);
        float4 k[4];
        #pragma unroll
        for (int q = 0; q < 4; q++) k[q] = row[lane + 32 * q];
        float acc = 0.f;
        #pragma unroll
        for (int q = 0; q < 4; q++) {
            k[q].x *= (ci + d4c[q].x); k[q].y *= (ci + d4c[q].y);
            k[q].z *= (ci + d4c[q].z); k[q].w *= (ci + d4c[q].w);
            row[lane + 32 * q] = k[q];
            acc += k[q].x + k[q].y + k[q].z + k[q].w;
        }
        #pragma unroll
        for (int off = 16; off; off >>= 1) acc += __shfl_xor_sync(0xffffffffu, acc, off);
        float u = 1.f / acc;                       // all lanes have it
        if (lane == 0) g_u[b * NN + i] = u;
        #pragma unroll
        for (int q = 0; q < 4; q++) {
            colacc[q].x += k[q].x * u; colacc[q].y += k[q].y * u;
            colacc[q].z += k[q].z * u; colacc[q].w += k[q].w * u;
        }
    }
    #pragma unroll
    for (int q = 0; q < 4; q++)
        *(float4*)&colsm[w][(lane + 32 * q) * 4] = colacc[q];
    __syncthreads();
    #pragma unroll
    for (int h = 0; h < 2; h++) {
        int j = tid + h * 256;
        float s = 0.f;
        #pragma unroll
        for (int ww = 0; ww < 8; ww++) s += colsm[ww][j];
        g_part[0][ic][b * NN + j] = s;
    }
}

// Iterations t = 1..NITER-1: same pass without the scaling.
__global__ __launch_bounds__(256) void k_iter(int t) {
    __shared__ __align__(16) float vloc[NN];
    __shared__ __align__(16) float colsm[8][NN];
    int b = blockIdx.y, ic = blockIdx.x, tid = threadIdx.x;
    int w = tid >> 5, lane = tid & 31;
    const float* P = &g_part[(t - 1) & 1][0][0];
    #pragma unroll
    for (int h = 0; h < 2; h++) {
        int j = tid + h * 256;
        float s = 0.f;
        #pragma unroll
        for (int sl = 0; sl < 8; sl++) s += P[sl * (BB * NN) + b * NN + j];
        vloc[j] = 1.f / s;
    }
    __syncthreads();
    const float4* vl4 = (const float4*)vloc;
    float4 v4c[4];
    #pragma unroll
    for (int q = 0; q < 4; q++) v4c[q] = vl4[lane + 32 * q];

    float4 colacc[4];
    #pragma unroll
    for (int q = 0; q < 4; q++) colacc[q] = make_float4(0.f, 0.f, 0.f, 0.f);

    #pragma unroll 4
    for (int rr = 0; rr < 8; rr++) {
        int i = ic * 64 + w * 8 + rr;
        const float4* row = (const float4*)(g_K + ((size_t)b * NN + i) * NN);
        float4 k[4];
        #pragma unroll
        for (int q = 0; q < 4; q++) k[q] = row[lane + 32 * q];
        float acc = 0.f;
        #pragma unroll
        for (int q = 0; q < 4; q++)
            acc += k[q].x * v4c[q].x + k[q].y * v4c[q].y
                 + k[q].z * v4c[q].z + k[q].w * v4c[q].w;
        #pragma unroll
        for (int off = 16; off; off >>= 1) acc += __shfl_xor_sync(0xffffffffu, acc, off);
        float u = 1.f / acc;
        if (lane == 0) g_u[b * NN + i] = u;
        #pragma unroll
        for (int q = 0; q < 4; q++) {
            colacc[q].x += k[q].x * u; colacc[q].y += k[q].y * u;
            colacc[q].z += k[q].z * u; colacc[q].w += k[q].w * u;
        }
    }
    #pragma unroll
    for (int q = 0; q < 4; q++)
        *(float4*)&colsm[w][(lane + 32 * q) * 4] = colacc[q];
    __syncthreads();
    float* Pw = &g_part[t & 1][0][0];
    #pragma unroll
    for (int h = 0; h < 2; h++) {
        int j = tid + h * 256;
        float s = 0.f;
        #pragma unroll
        for (int ww = 0; ww < 8; ww++) s += colsm[ww][j];
        Pw[ic * (BB * NN) + b * NN + j] = s;
    }
}

// ---------------- K6: P = u_i * K_ij * v_j  ->  d_out ----------------------
__global__ __launch_bounds__(256) void k_writeP(float* __restrict__ out) {
    __shared__ __align__(16) float vloc[NN];
    int b = blockIdx.y, ic = blockIdx.x, tid = threadIdx.x;
    const float* P = &g_part[(NITER - 1) & 1][0][0];
    #pragma unroll
    for (int h = 0; h < 2; h++) {
        int j = tid + h * 256;
        float s = 0.f;
        #pragma unroll
        for (int sl = 0; sl < 8; sl++) s += P[sl * (BB * NN) + b * NN + j];
        vloc[j] = 1.f / s;
    }
    __syncthreads();
    int half = tid >> 7;                  // 0/1: which row of the pair
    int c4   = tid & 127;                 // float4 column
    const float4* vl4 = (const float4*)vloc;
    float4 v4 = vl4[c4];
    #pragma unroll 2
    for (int rr = 0; rr < 32; rr++) {
        int i = ic * 64 + rr * 2 + half;
        float ui = g_u[b * NN + i];
        const float4* Kr = (const float4*)(g_K + ((size_t)b * NN + i) * NN);
        float4*       Or = (float4*)(out + ((size_t)b * NN + i) * NN);
        float4 k4 = Kr[c4];
        Or[c4] = make_float4(ui * k4.x * v4.x, ui * k4.y * v4.y,
                             ui * k4.z * v4.z, ui * k4.w * v4.w);
    }
}

// ---------------- launch ---------------------------------------------------
extern "C" void kernel_launch(void* const* d_in, const int* in_sizes, int n_in,
                              void* d_out, int out_size) {
    const float* nodeIn  = (const float*)d_in[0];
    const void*  mask    = d_in[1];
    const float* nodeOut = (const float*)d_in[2];
    const float* pad     = (const float*)d_in[3];
    const float* pos     = (const float*)d_in[4];
    const float* Wa      = (const float*)d_in[5];
    const float* Wb      = (const float*)d_in[6];
    const float* waff    = (const float*)d_in[7];
    const float* baff    = (const float*)d_in[8];

    k_init<<<1, 512>>>(mask);
    k_gemm_ab<<<dim3(512, 1, 2), 256>>>(nodeIn, mask, nodeOut, pad, pos, Wa, Wb, waff);
    k_aff_exp<<<dim3(4, 4, 64), 256>>>(baff);
    k_iter0<<<dim3(8, 64), 256>>>();              // scale + row-norm + col-partials
    for (int t = 1; t < NITER; t++)
        k_iter<<<dim3(8, 64), 256>>>(t);          // one K pass per iteration
    k_writeP<<<dim3(8, 64), 256>>>((float*)d_out);
}

// round 15
// speedup vs baseline: 1.0179x; 1.0179x over previous
#include <cuda_runtime.h>
#include <cuda_fp16.h>
#include <stdint.h>

#define BB 64
#define NN 512
#define DD 256
#define EE 128
#define NITER 20

// ---------------- device scratch (no allocations allowed) ----------------
__device__ float  g_a [BB * NN * EE];           // 16 MB  a = (x_out @ W_a) * w_aff
__device__ float  g_bm[BB * NN * EE];           // 16 MB  b = x_in @ W_b
__device__ float  g_K [BB * NN * NN];           // 67 MB  E = exp(aff) (fp32)
__device__ __half g_Kh[(size_t)BB * NN * NN];   // 34 MB  scaled K (fp16, L2-resident)
__device__ float  g_rp[4][BB * NN];             // per-jblock rowsum partials of E
__device__ float  g_cp[4][BB * NN];             // per-iblock colsum partials of E
__device__ float  g_u [BB * NN];                // row scalings
__device__ float  g_part[2][16][BB * NN];       // ping-pong per-slab colsum partials
__device__ int    g_mask_mode;                  // 0=int32, 1=float32, 2=byte

// ---------------- f32x2 helpers (Blackwell packed fp32 FMA) ----------------
__device__ __forceinline__ unsigned long long pk2(float lo, float hi) {
    unsigned long long r;
    asm("mov.b64 %0, {%1,%2};" : "=l"(r) : "f"(lo), "f"(hi));
    return r;
}
__device__ __forceinline__ float2 upk2(unsigned long long v) {
    float2 f;
    asm("mov.b64 {%0,%1}, %2;" : "=f"(f.x), "=f"(f.y) : "l"(v));
    return f;
}
__device__ __forceinline__ unsigned long long fma2(unsigned long long a,
                                                   unsigned long long b,
                                                   unsigned long long c) {
    unsigned long long d;
    asm("fma.rn.f32x2 %0, %1, %2, %3;" : "=l"(d) : "l"(a), "l"(b), "l"(c));
    return d;
}
// unpack uint4 (8 halfs) -> 8 floats
__device__ __forceinline__ void h8f(uint4 h, float* f) {
    const __half2* p = (const __half2*)&h;
    float2 t;
    t = __half22float2(p[0]); f[0] = t.x; f[1] = t.y;
    t = __half22float2(p[1]); f[2] = t.x; f[3] = t.y;
    t = __half22float2(p[2]); f[4] = t.x; f[5] = t.y;
    t = __half22float2(p[3]); f[6] = t.x; f[7] = t.y;
}

// ---------------- init: detect mask dtype ----------------------------------
__global__ void k_init(const void* __restrict__ mask) {
    int t = threadIdx.x;                          // 1 block, 512 threads
    __shared__ int okInt, okFlt;
    if (t == 0) { okInt = 1; okFlt = 1; }
    __syncthreads();
    const int*   mi = (const int*)mask;
    const float* mf = (const float*)mask;
    int li = 1, lf = 1;
    for (int q = t; q < 2048; q += 512) {         // 8 KB probe, safe for all layouts
        int v = mi[q];   if (v != 0 && v != 1)     li = 0;
        float f = mf[q]; if (f != 0.f && f != 1.f) lf = 0;
    }
    if (!li) atomicAnd(&okInt, 0);
    if (!lf) atomicAnd(&okFlt, 0);
    __syncthreads();
    if (t == 0) g_mask_mode = okInt ? 0 : (okFlt ? 1 : 2);
}

// ---------------- K1: a = (x_out @ W_a)*w_aff  and  b = x_in @ W_b ---------
__global__ __launch_bounds__(256) void k_gemm_ab(
    const float* __restrict__ nodeIn, const void* __restrict__ mask,
    const float* __restrict__ nodeOut, const float* __restrict__ pad,
    const float* __restrict__ pos, const float* __restrict__ Wa,
    const float* __restrict__ Wb, const float* __restrict__ waff)
{
    __shared__ __align__(16) float Xs[32][66];    // k-major, transposed X tile
    __shared__ __align__(16) float Ws[32][128];   // [k][col]
    int tid  = threadIdx.x;
    int z    = blockIdx.z;                        // 0 -> a, 1 -> b
    int row0 = blockIdx.x * 64;
    int colg = tid & 31;                          // 32 col groups of 4
    int rowg = tid >> 5;                          // 8 row groups of 8
    const float* W = z ? Wb : Wa;
    int mode = g_mask_mode;

    unsigned long long acc[4][4];
    #pragma unroll
    for (int p = 0; p < 4; p++)
        #pragma unroll
        for (int c = 0; c < 4; c++) acc[p][c] = 0ull;

    for (int kb = 0; kb < 8; kb++) {
        int k0 = kb * 32;
        #pragma unroll
        for (int it = 0; it < 8; it++) {          // 2048 floats of X (with transform)
            int l = tid + it * 256;
            int kk = l & 31, r = l >> 5;
            int grow = row0 + r;
            float v;
            if (z == 0) {
                v = nodeOut[grow * DD + k0 + kk] + pos[(grow & (NN - 1)) * DD + k0 + kk];
            } else {
                bool m;
                if (mode == 0)      m = ((const int*)mask)[grow] != 0;
                else if (mode == 1) m = ((const float*)mask)[grow] != 0.f;
                else                m = ((const unsigned char*)mask)[grow] != 0;
                v = m ? pad[k0 + kk] : nodeIn[grow * DD + k0 + kk];
            }
            Xs[kk][r] = v;
        }
        #pragma unroll
        for (int it = 0; it < 4; it++) {          // 4096 floats of W as float4
            int l  = tid + it * 256;
            int kk = l >> 5;
            int c4 = (l & 31) * 4;
            *(float4*)&Ws[kk][c4] = *(const float4*)&W[(k0 + kk) * EE + c4];
        }
        __syncthreads();
        #pragma unroll
        for (int kk = 0; kk < 32; kk++) {
            unsigned long long a2[4];
            #pragma unroll
            for (int p = 0; p < 4; p++)
                a2[p] = *(const unsigned long long*)&Xs[kk][rowg * 8 + 2 * p];
            float4 b4 = *(const float4*)&Ws[kk][colg * 4];
            unsigned long long bb0 = pk2(b4.x, b4.x), bb1 = pk2(b4.y, b4.y);
            unsigned long long bb2 = pk2(b4.z, b4.z), bb3 = pk2(b4.w, b4.w);
            #pragma unroll
            for (int p = 0; p < 4; p++) {
                acc[p][0] = fma2(a2[p], bb0, acc[p][0]);
                acc[p][1] = fma2(a2[p], bb1, acc[p][1]);
                acc[p][2] = fma2(a2[p], bb2, acc[p][2]);
                acc[p][3] = fma2(a2[p], bb3, acc[p][3]);
            }
        }
        __syncthreads();
    }
    float w0 = 1.f, w1 = 1.f, w2 = 1.f, w3 = 1.f;
    if (z == 0) {
        w0 = waff[colg * 4 + 0]; w1 = waff[colg * 4 + 1];
        w2 = waff[colg * 4 + 2]; w3 = waff[colg * 4 + 3];
    }
    float* out = z ? g_bm : g_a;
    #pragma unroll
    for (int p = 0; p < 4; p++) {
        float2 c0 = upk2(acc[p][0]), c1 = upk2(acc[p][1]);
        float2 c2 = upk2(acc[p][2]), c3 = upk2(acc[p][3]);
        int r0 = row0 + rowg * 8 + 2 * p;
        float4 lo = make_float4(c0.x * w0, c1.x * w1, c2.x * w2, c3.x * w3);
        float4 hi = make_float4(c0.y * w0, c1.y * w1, c2.y * w2, c3.y * w3);
        *(float4*)&out[(size_t)r0 * EE + colg * 4]       = lo;
        *(float4*)&out[(size_t)(r0 + 1) * EE + colg * 4] = hi;
    }
}

// ---------------- K2: E = exp(a·b^T + b_aff), deterministic partial sums ---
__global__ __launch_bounds__(256, 2) void k_aff_exp(const float* __restrict__ baff_p)
{
    __shared__ __align__(16) float As[32][132];   // [e][i]
    __shared__ __align__(16) float Bs[32][132];   // [e][j]
    int tid = threadIdx.x;
    int b  = blockIdx.z;
    int i0 = blockIdx.y * 128, j0 = blockIdx.x * 128;
    int tx = tid & 15, ty = tid >> 4;             // cols: tx*4 and 64+tx*4 ; rows: ty*8

    unsigned long long acc[4][8];
    #pragma unroll
    for (int p = 0; p < 4; p++)
        #pragma unroll
        for (int c = 0; c < 8; c++) acc[p][c] = 0ull;

    const float* Ab = g_a  + (size_t)(b * NN + i0) * EE;
    const float* Bb = g_bm + (size_t)(b * NN + j0) * EE;

    for (int kb = 0; kb < 4; kb++) {
        int e0 = kb * 32;
        #pragma unroll
        for (int it = 0; it < 16; it++) {         // 4096 floats each, transposed
            int l = tid + it * 256;
            int e = l & 31, r = l >> 5;
            As[e][r] = Ab[r * EE + e0 + e];
            Bs[e][r] = Bb[r * EE + e0 + e];
        }
        __syncthreads();
        #pragma unroll
        for (int e = 0; e < 32; e++) {
            unsigned long long a2[4];
            #pragma unroll
            for (int p = 0; p < 4; p++)
                a2[p] = *(const unsigned long long*)&As[e][ty * 8 + 2 * p];
            float4 bA = *(const float4*)&Bs[e][tx * 4];
            float4 bB = *(const float4*)&Bs[e][64 + tx * 4];
            unsigned long long bb[8];
            bb[0] = pk2(bA.x, bA.x); bb[1] = pk2(bA.y, bA.y);
            bb[2] = pk2(bA.z, bA.z); bb[3] = pk2(bA.w, bA.w);
            bb[4] = pk2(bB.x, bB.x); bb[5] = pk2(bB.y, bB.y);
            bb[6] = pk2(bB.z, bB.z); bb[7] = pk2(bB.w, bB.w);
            #pragma unroll
            for (int p = 0; p < 4; p++)
                #pragma unroll
                for (int c = 0; c < 8; c++)
                    acc[p][c] = fma2(a2[p], bb[c], acc[p][c]);
        }
        __syncthreads();
    }

    float baff = *baff_p;
    float rs[8];
    #pragma unroll
    for (int r = 0; r < 8; r++) rs[r] = 0.f;
    float csA[4] = {0.f, 0.f, 0.f, 0.f}, csB[4] = {0.f, 0.f, 0.f, 0.f};
    float* Kb = g_K + (size_t)b * NN * NN;

    #pragma unroll
    for (int p = 0; p < 4; p++) {
        float2 vA[4], vB[4];
        #pragma unroll
        for (int c = 0; c < 4; c++) { vA[c] = upk2(acc[p][c]); vB[c] = upk2(acc[p][4 + c]); }
        float4 loA, hiA, loB, hiB;
        loA.x = __expf(vA[0].x + baff); loA.y = __expf(vA[1].x + baff);
        loA.z = __expf(vA[2].x + baff); loA.w = __expf(vA[3].x + baff);
        hiA.x = __expf(vA[0].y + baff); hiA.y = __expf(vA[1].y + baff);
        hiA.z = __expf(vA[2].y + baff); hiA.w = __expf(vA[3].y + baff);
        loB.x = __expf(vB[0].x + baff); loB.y = __expf(vB[1].x + baff);
        loB.z = __expf(vB[2].x + baff); loB.w = __expf(vB[3].x + baff);
        hiB.x = __expf(vB[0].y + baff); hiB.y = __expf(vB[1].y + baff);
        hiB.z = __expf(vB[2].y + baff); hiB.w = __expf(vB[3].y + baff);
        int il = ty * 8 + 2 * p;
        rs[2 * p]     += loA.x + loA.y + loA.z + loA.w + loB.x + loB.y + loB.z + loB.w;
        rs[2 * p + 1] += hiA.x + hiA.y + hiA.z + hiA.w + hiB.x + hiB.y + hiB.z + hiB.w;
        csA[0] += loA.x + hiA.x; csA[1] += loA.y + hiA.y;
        csA[2] += loA.z + hiA.z; csA[3] += loA.w + hiA.w;
        csB[0] += loB.x + hiB.x; csB[1] += loB.y + hiB.y;
        csB[2] += loB.z + hiB.z; csB[3] += loB.w + hiB.w;
        *(float4*)&Kb[(size_t)(i0 + il) * NN + j0 + tx * 4]           = loA;
        *(float4*)&Kb[(size_t)(i0 + il) * NN + j0 + 64 + tx * 4]      = loB;
        *(float4*)&Kb[(size_t)(i0 + il + 1) * NN + j0 + tx * 4]       = hiA;
        *(float4*)&Kb[(size_t)(i0 + il + 1) * NN + j0 + 64 + tx * 4]  = hiB;
    }

    // ---- deterministic row partials: butterfly over the 16-lane tx group ----
    #pragma unroll
    for (int r8 = 0; r8 < 8; r8++) {
        float v = rs[r8];
        v += __shfl_xor_sync(0xffffffffu, v, 1);
        v += __shfl_xor_sync(0xffffffffu, v, 2);
        v += __shfl_xor_sync(0xffffffffu, v, 4);
        v += __shfl_xor_sync(0xffffffffu, v, 8);
        rs[r8] = v;
    }
    if (tx == 0) {
        float* rp = &g_rp[blockIdx.x][0] + b * NN + i0;
        #pragma unroll
        for (int p = 0; p < 4; p++) {
            rp[ty * 8 + 2 * p]     = rs[2 * p];
            rp[ty * 8 + 2 * p + 1] = rs[2 * p + 1];
        }
    }

    // ---- deterministic col partials: per-ty smem rows, fixed-order sum ------
    __syncthreads();
    float* colp = &As[0][0];                       // [16][132] layout
    #pragma unroll
    for (int c = 0; c < 4; c++) {
        colp[ty * 132 + tx * 4 + c]      = csA[c];
        colp[ty * 132 + 64 + tx * 4 + c] = csB[c];
    }
    __syncthreads();
    if (tid < 128) {
        float s = 0.f;
        #pragma unroll
        for (int yy = 0; yy < 16; yy++) s += colp[yy * 132 + tid];
        g_cp[blockIdx.y][b * NN + j0 + tid] = s;
    }
}

// ---------------- Sinkhorn: 32-row slabs, grid (16, 64), 8 warps x 4 rows ---
// Iteration 0: read fp32 E, scale by (c_i + d_j), write fp16 K, compute
// u = 1/rowsum and per-slab colsum partials of K^T u. Single quantization.
__global__ __launch_bounds__(256) void k_iter0() {
    __shared__ __align__(16) float dloc[NN];
    __shared__ __align__(16) float colsm[8][NN];
    int b = blockIdx.y, ic = blockIdx.x, tid = threadIdx.x;
    int w = tid >> 5, lane = tid & 31;
    #pragma unroll
    for (int h = 0; h < 2; h++) {
        int j = tid + h * 256;
        float s = g_cp[0][b * NN + j] + g_cp[1][b * NN + j]
                + g_cp[2][b * NN + j] + g_cp[3][b * NN + j];
        dloc[j] = 0.5f / s;
    }
    __syncthreads();
    const float4* dl4 = (const float4*)dloc;
    float4 d4c[4];
    #pragma unroll
    for (int q = 0; q < 4; q++) d4c[q] = dl4[lane + 32 * q];

    float4 colacc[4];
    #pragma unroll
    for (int q = 0; q < 4; q++) colacc[q] = make_float4(0.f, 0.f, 0.f, 0.f);

    #pragma unroll 4
    for (int rr = 0; rr < 4; rr++) {
        int i = ic * 32 + w * 4 + rr;
        float rsum = g_rp[0][b * NN + i] + g_rp[1][b * NN + i]
                   + g_rp[2][b * NN + i] + g_rp[3][b * NN + i];
        float ci = 0.5f / rsum;
        const float4* row = (const float4*)(g_K + ((size_t)b * NN + i) * NN);
        __half* hrow = &g_Kh[((size_t)b * NN + i) * NN];
        float4 k[4];
        #pragma unroll
        for (int q = 0; q < 4; q++) k[q] = row[lane + 32 * q];
        float acc = 0.f;
        #pragma unroll
        for (int q = 0; q < 4; q++) {
            k[q].x *= (ci + d4c[q].x); k[q].y *= (ci + d4c[q].y);
            k[q].z *= (ci + d4c[q].z); k[q].w *= (ci + d4c[q].w);
            __half2 h0 = __floats2half2_rn(k[q].x, k[q].y);
            __half2 h1 = __floats2half2_rn(k[q].z, k[q].w);
            uint2 hv = make_uint2(*(unsigned*)&h0, *(unsigned*)&h1);
            *(uint2*)&hrow[(lane + 32 * q) * 4] = hv;
            acc += k[q].x + k[q].y + k[q].z + k[q].w;
        }
        #pragma unroll
        for (int off = 16; off; off >>= 1) acc += __shfl_xor_sync(0xffffffffu, acc, off);
        float u = 1.f / acc;
        if (lane == 0) g_u[b * NN + i] = u;
        #pragma unroll
        for (int q = 0; q < 4; q++) {
            colacc[q].x += k[q].x * u; colacc[q].y += k[q].y * u;
            colacc[q].z += k[q].z * u; colacc[q].w += k[q].w * u;
        }
    }
    #pragma unroll
    for (int q = 0; q < 4; q++)
        *(float4*)&colsm[w][(lane + 32 * q) * 4] = colacc[q];
    __syncthreads();
    #pragma unroll
    for (int h = 0; h < 2; h++) {
        int j = tid + h * 256;
        float s = 0.f;
        #pragma unroll
        for (int ww = 0; ww < 8; ww++) s += colsm[ww][j];
        g_part[0][ic][b * NN + j] = s;
    }
}

// Iterations t = 1..NITER-1: fp16 K, fp32 math. Lane covers 8 contiguous
// cols at (lane+32q)*8 for q=0,1 (two uint4 = 16 halfs per row).
__global__ __launch_bounds__(256) void k_iter(int t) {
    __shared__ __align__(16) float vloc[NN];
    __shared__ __align__(16) float colsm[8][NN];
    int b = blockIdx.y, ic = blockIdx.x, tid = threadIdx.x;
    int w = tid >> 5, lane = tid & 31;
    const float* P = &g_part[(t - 1) & 1][0][0];
    #pragma unroll
    for (int h = 0; h < 2; h++) {
        int j = tid + h * 256;
        float s = 0.f;
        #pragma unroll
        for (int sl = 0; sl < 16; sl++) s += P[sl * (BB * NN) + b * NN + j];
        vloc[j] = 1.f / s;
    }
    __syncthreads();
    const float4* vl4 = (const float4*)vloc;
    float4 va[2][2];
    #pragma unroll
    for (int q = 0; q < 2; q++) {
        va[q][0] = vl4[(lane + 32 * q) * 2];
        va[q][1] = vl4[(lane + 32 * q) * 2 + 1];
    }

    float colacc[2][8];
    #pragma unroll
    for (int q = 0; q < 2; q++)
        #pragma unroll
        for (int c = 0; c < 8; c++) colacc[q][c] = 0.f;

    #pragma unroll 4
    for (int rr = 0; rr < 4; rr++) {
        int i = ic * 32 + w * 4 + rr;
        const __half* hrow = &g_Kh[((size_t)b * NN + i) * NN];
        uint4 kh[2];
        #pragma unroll
        for (int q = 0; q < 2; q++)
            kh[q] = *(const uint4*)&hrow[(lane + 32 * q) * 8];
        float kf[2][8];
        h8f(kh[0], kf[0]); h8f(kh[1], kf[1]);
        float acc = 0.f;
        #pragma unroll
        for (int q = 0; q < 2; q++) {
            acc += kf[q][0] * va[q][0].x + kf[q][1] * va[q][0].y
                 + kf[q][2] * va[q][0].z + kf[q][3] * va[q][0].w
                 + kf[q][4] * va[q][1].x + kf[q][5] * va[q][1].y
                 + kf[q][6] * va[q][1].z + kf[q][7] * va[q][1].w;
        }
        #pragma unroll
        for (int off = 16; off; off >>= 1) acc += __shfl_xor_sync(0xffffffffu, acc, off);
        float u = 1.f / acc;
        if (lane == 0) g_u[b * NN + i] = u;
        #pragma unroll
        for (int q = 0; q < 2; q++)
            #pragma unroll
            for (int c = 0; c < 8; c++) colacc[q][c] += kf[q][c] * u;
    }
    #pragma unroll
    for (int q = 0; q < 2; q++) {
        *(float4*)&colsm[w][(lane + 32 * q) * 8]     = *(float4*)&colacc[q][0];
        *(float4*)&colsm[w][(lane + 32 * q) * 8 + 4] = *(float4*)&colacc[q][4];
    }
    __syncthreads();
    float* Pw = &g_part[t & 1][0][0];
    #pragma unroll
    for (int h = 0; h < 2; h++) {
        int j = tid + h * 256;
        float s = 0.f;
        #pragma unroll
        for (int ww = 0; ww < 8; ww++) s += colsm[ww][j];
        Pw[ic * (BB * NN) + b * NN + j] = s;
    }
}

// ---------------- K6: P = u_i * K_ij * v_j  ->  d_out (fp32) ---------------
__global__ __launch_bounds__(256) void k_writeP(float* __restrict__ out) {
    __shared__ __align__(16) float vloc[NN];
    int b = blockIdx.y, ic = blockIdx.x, tid = threadIdx.x;
    int w = tid >> 5, lane = tid & 31;
    const float* P = &g_part[(NITER - 1) & 1][0][0];
    #pragma unroll
    for (int h = 0; h < 2; h++) {
        int j = tid + h * 256;
        float s = 0.f;
        #pragma unroll
        for (int sl = 0; sl < 16; sl++) s += P[sl * (BB * NN) + b * NN + j];
        vloc[j] = 1.f / s;
    }
    __syncthreads();
    const float4* vl4 = (const float4*)vloc;
    float4 va[2][2];
    #pragma unroll
    for (int q = 0; q < 2; q++) {
        va[q][0] = vl4[(lane + 32 * q) * 2];
        va[q][1] = vl4[(lane + 32 * q) * 2 + 1];
    }
    #pragma unroll 4
    for (int rr = 0; rr < 4; rr++) {
        int i = ic * 32 + w * 4 + rr;
        float ui = g_u[b * NN + i];
        const __half* hrow = &g_Kh[((size_t)b * NN + i) * NN];
        float* orow = out + ((size_t)b * NN + i) * NN;
        #pragma unroll
        for (int q = 0; q < 2; q++) {
            uint4 kh = *(const uint4*)&hrow[(lane + 32 * q) * 8];
            float kf[8];
            h8f(kh, kf);
            float4 o0 = make_float4(ui * kf[0] * va[q][0].x, ui * kf[1] * va[q][0].y,
                                    ui * kf[2] * va[q][0].z, ui * kf[3] * va[q][0].w);
            float4 o1 = make_float4(ui * kf[4] * va[q][1].x, ui * kf[5] * va[q][1].y,
                                    ui * kf[6] * va[q][1].z, ui * kf[7] * va[q][1].w);
            *(float4*)&orow[(lane + 32 * q) * 8]     = o0;
            *(float4*)&orow[(lane + 32 * q) * 8 + 4] = o1;
        }
    }
}

// ---------------- launch ---------------------------------------------------
extern "C" void kernel_launch(void* const* d_in, const int* in_sizes, int n_in,
                              void* d_out, int out_size) {
    const float* nodeIn  = (const float*)d_in[0];
    const void*  mask    = d_in[1];
    const float* nodeOut = (const float*)d_in[2];
    const float* pad     = (const float*)d_in[3];
    const float* pos     = (const float*)d_in[4];
    const float* Wa      = (const float*)d_in[5];
    const float* Wb      = (const float*)d_in[6];
    const float* waff    = (const float*)d_in[7];
    const float* baff    = (const float*)d_in[8];

    k_init<<<1, 512>>>(mask);
    k_gemm_ab<<<dim3(512, 1, 2), 256>>>(nodeIn, mask, nodeOut, pad, pos, Wa, Wb, waff);
    k_aff_exp<<<dim3(4, 4, 64), 256>>>(baff);
    k_iter0<<<dim3(16, 64), 256>>>();             // scale + fp16 pack + iter 0
    for (int t = 1; t < NITER; t++)
        k_iter<<<dim3(16, 64), 256>>>(t);         // one fp16 K pass per iteration
    k_writeP<<<dim3(16, 64), 256>>>((float*)d_out);
}